// round 5
// baseline (speedup 1.0000x reference)
#include <cuda_runtime.h>
#include <cuda_fp16.h>
#include <cstdint>

// ============================================================================
// LinearWithLoRA on GB300 (PTX target sm_103 baseline: NO tcgen05/TMEM).
// Fold LoRA into W (rank-16), then one fp16 mma.sync GEMM, fp32 accumulate:
//   out[8192,2048] = x[8192,2048] @ W_eff[2048,2048]^T + b
// fp16 single-pass: rel err ~ 2^-11 RMS ~ 3.5e-4 < 1e-3 threshold.
// ============================================================================

#define M_TOTAL 8192
#define N_TOTAL 2048
#define K_TOTAL 2048
#define BM 128
#define BN 128
#define BK 64                       // fp16 per K-chunk (128 B/row, swizzled)
#define NCHUNK (K_TOTAL / BK)       // 32

#define STAGE_BYTES 32768           // A 16K + B 16K
#define OFF_A 0
#define OFF_B 16384
#define SMEM_TOTAL (2 * STAGE_BYTES)

// ---- scratch (static device globals; allocation is forbidden) ----
__device__ __align__(16) __half g_xh[(size_t)M_TOTAL * K_TOTAL];
__device__ __align__(16) __half g_wh[(size_t)N_TOTAL * K_TOTAL];

// ---- helpers ----
__device__ __forceinline__ uint32_t smem_u32(const void* p) {
    uint32_t a;
    asm("{ .reg .u64 t; cvta.to.shared.u64 t, %1; cvt.u32.u64 %0, t; }"
        : "=r"(a) : "l"(p));
    return a;
}

__device__ __forceinline__ void cp16(uint32_t dst, const void* src) {
    asm volatile("cp.async.cg.shared.global [%0], [%1], 16;" :: "r"(dst), "l"(src));
}

// ldmatrix x4: 4 8x8 b16 matrices, one 16B-row address per lane
__device__ __forceinline__ void ldsm4(uint32_t& r0, uint32_t& r1,
                                      uint32_t& r2, uint32_t& r3, uint32_t addr) {
    asm volatile("ldmatrix.sync.aligned.m8n8.x4.shared.b16 {%0,%1,%2,%3}, [%4];"
                 : "=r"(r0), "=r"(r1), "=r"(r2), "=r"(r3) : "r"(addr));
}

// D += A*B, m16n8k16 fp16 inputs fp32 accum
__device__ __forceinline__ void mma16816(float* d, const uint32_t* a, const uint32_t* b) {
    asm volatile(
        "mma.sync.aligned.m16n8k16.row.col.f32.f16.f16.f32 "
        "{%0,%1,%2,%3}, {%4,%5,%6,%7}, {%8,%9}, {%0,%1,%2,%3};"
        : "+f"(d[0]), "+f"(d[1]), "+f"(d[2]), "+f"(d[3])
        : "r"(a[0]), "r"(a[1]), "r"(a[2]), "r"(a[3]), "r"(b[0]), "r"(b[1]));
}

// ============================================================================
// Prep: fold LoRA into W; convert x and W_eff to fp16.
// ============================================================================
struct H4 { __half2 a, b; };   // 8 bytes

__device__ __forceinline__ H4 to_h4(float4 v) {
    H4 h;
    h.a = __floats2half2_rn(v.x, v.y);
    h.b = __floats2half2_rn(v.z, v.w);
    return h;
}

__global__ void prep_x_kernel(const float4* __restrict__ x) {
    int idx = blockIdx.x * 256 + threadIdx.x;     // over 8192*2048/4
    ((H4*)g_xh)[idx] = to_h4(x[idx]);
}

__global__ void prep_w_kernel(const float4* __restrict__ W,
                              const float* __restrict__ lA,
                              const float* __restrict__ lB) {
    int idx = blockIdx.x * 256 + threadIdx.x;     // over 2048*2048/4
    int o = idx >> 9;                             // 512 float4 per row
    int d = (idx & 511) * 4;
    float4 w = W[idx];
    float a0 = 0.f, a1 = 0.f, a2 = 0.f, a3 = 0.f;
#pragma unroll
    for (int r = 0; r < 16; r++) {
        float bb = lB[o * 16 + r];
        const float4 av = *(const float4*)(lA + r * 2048 + d);
        a0 += bb * av.x; a1 += bb * av.y; a2 += bb * av.z; a3 += bb * av.w;
    }
    w.x += 2.0f * a0; w.y += 2.0f * a1;           // SCALING = 32/16
    w.z += 2.0f * a2; w.w += 2.0f * a3;
    ((H4*)g_wh)[idx] = to_h4(w);
}

// ============================================================================
// GEMM: CTA 128x128, 8 warps as 2(M) x 4(N), warp tile 64x32.
// SMEM: row = 128 B (64 fp16) per tile row, chunk-XOR swizzle:
//   byte(row, chunk16) = row*128 + (chunk ^ (row&7))*16      -> LDSM conflict-free
// ============================================================================
__device__ __forceinline__ void load_stage(uint32_t sbase, int kc,
                                           int mBase, int nBase, int tid) {
    const int kcol = kc * BK;
#pragma unroll
    for (int i = 0; i < 4; i++) {                 // A: 128 rows x 8 x 16B
        int idx = tid + i * 256;
        int row = idx >> 3;
        int c = idx & 7;
        uint32_t sw = (uint32_t)(c ^ (row & 7)) * 16u + (uint32_t)row * 128u;
        cp16(sbase + OFF_A + sw, g_xh + (size_t)(mBase + row) * K_TOTAL + kcol + c * 8);
    }
#pragma unroll
    for (int i = 0; i < 4; i++) {                 // B: 128 rows x 8 x 16B
        int idx = tid + i * 256;
        int row = idx >> 3;
        int c = idx & 7;
        uint32_t sw = (uint32_t)(c ^ (row & 7)) * 16u + (uint32_t)row * 128u;
        cp16(sbase + OFF_B + sw, g_wh + (size_t)(nBase + row) * K_TOTAL + kcol + c * 8);
    }
    asm volatile("cp.async.commit_group;" ::: "memory");
}

__global__ void __launch_bounds__(256, 2)
gemm_kernel(const float* __restrict__ bias, float* __restrict__ out) {
    extern __shared__ char smem[];
    const uint32_t sbase = smem_u32(smem);
    const int tid = threadIdx.x;
    const int lane = tid & 31;
    const int wid = tid >> 5;
    const int warpM = wid >> 2;                  // 0..1  -> 64-row slice
    const int warpN = wid & 3;                   // 0..3  -> 32-col slice
    const int mBase = blockIdx.y * BM;
    const int nBase = blockIdx.x * BN;

    float acc[4][4][4];                          // [mt][nt][frag]
#pragma unroll
    for (int i = 0; i < 4; i++)
#pragma unroll
        for (int j = 0; j < 4; j++)
#pragma unroll
            for (int k = 0; k < 4; k++) acc[i][j][k] = 0.f;

    // per-lane ldmatrix address components (row part), hoisted
    // A: row = warpM*64 + mt*16 + (lane & 15); chunk = 2*ks + (lane >> 4)
    //    -> matrices {r0-7/klo, r8-15/klo, r0-7/khi, r8-15/khi} = a0..a3 order
    const int aRow = warpM * 64 + (lane & 15);
    const int aChunkOff = lane >> 4;
    // B: row = warpN*32 + ntp*16 + ((lane>>4)<<3) + (lane & 7)
    //    chunk = 2*ks + ((lane>>3)&1)
    //    -> per n8-tile {klo, khi} = b0,b1 order
    const int bRow = warpN * 32 + ((lane >> 4) << 3) + (lane & 7);
    const int bChunkOff = (lane >> 3) & 1;

    load_stage(sbase, 0, mBase, nBase, tid);

    for (int c = 0; c < NCHUNK; c++) {
        const int s = c & 1;
        if (c + 1 < NCHUNK) {
            load_stage(sbase + (s ^ 1) * STAGE_BYTES, c + 1, mBase, nBase, tid);
            asm volatile("cp.async.wait_group 1;" ::: "memory");
        } else {
            asm volatile("cp.async.wait_group 0;" ::: "memory");
        }
        __syncthreads();

        const uint32_t stA = sbase + s * STAGE_BYTES + OFF_A;
        const uint32_t stB = sbase + s * STAGE_BYTES + OFF_B;

#pragma unroll
        for (int ks = 0; ks < 4; ks++) {
            uint32_t a[4][4];
            uint32_t b[4][2];
#pragma unroll
            for (int mt = 0; mt < 4; mt++) {
                int row = aRow + mt * 16;
                int ch = 2 * ks + aChunkOff;
                uint32_t addr = stA + (uint32_t)row * 128u
                              + (uint32_t)((ch ^ (row & 7)) << 4);
                ldsm4(a[mt][0], a[mt][1], a[mt][2], a[mt][3], addr);
            }
#pragma unroll
            for (int ntp = 0; ntp < 2; ntp++) {
                int row = bRow + ntp * 16;
                int ch = 2 * ks + bChunkOff;
                uint32_t addr = stB + (uint32_t)row * 128u
                              + (uint32_t)((ch ^ (row & 7)) << 4);
                ldsm4(b[2 * ntp][0], b[2 * ntp][1], b[2 * ntp + 1][0], b[2 * ntp + 1][1], addr);
            }
#pragma unroll
            for (int mt = 0; mt < 4; mt++)
#pragma unroll
                for (int nt = 0; nt < 4; nt++)
                    mma16816(acc[mt][nt], a[mt], b[nt]);
        }
        __syncthreads();
    }

    // ---- epilogue: registers -> out (+bias), float2 per frag-pair ----
    // frag: d0,d1 = (row = lane/4,     col = 2*(lane%4)+{0,1})
    //       d2,d3 = (row = lane/4 + 8, col same)
    {
        const int rBase = mBase + warpM * 64 + (lane >> 2);
        const int cBase = nBase + warpN * 32 + 2 * (lane & 3);
        float2 bv[4];
#pragma unroll
        for (int nt = 0; nt < 4; nt++) {
            bv[nt].x = __ldg(bias + cBase + nt * 8);
            bv[nt].y = __ldg(bias + cBase + nt * 8 + 1);
        }
#pragma unroll
        for (int mt = 0; mt < 4; mt++) {
            const size_t r0 = (size_t)(rBase + mt * 16) * N_TOTAL;
            const size_t r1 = r0 + 8 * N_TOTAL;
#pragma unroll
            for (int nt = 0; nt < 4; nt++) {
                const int col = cBase + nt * 8;
                float2 v0 = { acc[mt][nt][0] + bv[nt].x, acc[mt][nt][1] + bv[nt].y };
                float2 v1 = { acc[mt][nt][2] + bv[nt].x, acc[mt][nt][3] + bv[nt].y };
                *(float2*)(out + r0 + col) = v0;
                *(float2*)(out + r1 + col) = v1;
            }
        }
    }
}

// ============================================================================
// kernel_launch
// ============================================================================
extern "C" void kernel_launch(void* const* d_in, const int* in_sizes, int n_in,
                              void* d_out, int out_size) {
    const float* x  = (const float*)d_in[0];   // [4,2048,2048] -> [8192,2048]
    const float* W  = (const float*)d_in[1];   // [2048,2048]
    const float* b  = (const float*)d_in[2];   // [2048]
    const float* lA = (const float*)d_in[3];   // [16,2048]
    const float* lB = (const float*)d_in[4];   // [2048,16]
    float* out = (float*)d_out;

    prep_x_kernel<<<(M_TOTAL * K_TOTAL / 4) / 256, 256>>>((const float4*)x);
    prep_w_kernel<<<(N_TOTAL * K_TOTAL / 4) / 256, 256>>>((const float4*)W, lA, lB);

    cudaFuncSetAttribute(gemm_kernel,
                         cudaFuncAttributeMaxDynamicSharedMemorySize, SMEM_TOTAL);
    // x-fastest: 16 n-blocks sweep per m-row; W (8MB fp16) stays L2-resident
    dim3 grid(N_TOTAL / BN, M_TOTAL / BM);     // (16, 64)
    gemm_kernel<<<grid, 256, SMEM_TOTAL>>>(b, out);
}